// round 17
// baseline (speedup 1.0000x reference)
#include <cuda_runtime.h>
#include <cuda_bf16.h>
#include <cstdint>
#include <mma.h>
using namespace nvcuda;

#define RCH 64
#define GCH 128
#define ACH 80
#define SCH 64
#define TT 8192
#define BB 8
#define NPOS (BB*TT)          // 65536
#define NLAYERS 30
#define NT 64                 // positions per block tile
#define THR 544               // 16 consumer warps + 1 producer warp
#define NCHUNK 11             // 6 conv + 3 aux + 2 OW, K=32 each
#define WPERL (NCHUNK*128*32) // 45056

// stage buffer (bytes): Wh [0,10240) Wl [10240,20480)
//                       Xh [20480,25088) Xl [25088,29696)
#define BUFB 29696
#define SM_BUFS 1024          // buffers start (mbarriers live below)
#define SMEM_TOTAL (SM_BUFS + 3*BUFB)   // 90112

__device__ float g_xa[BB*RCH*TT];
__device__ float g_xb[BB*RCH*TT];
__device__ float g_skip[BB*SCH*TT];
__device__ __align__(16) __nv_bfloat16 g_xh0[BB*RCH*TT];
__device__ __align__(16) __nv_bfloat16 g_xl0[BB*RCH*TT];
__device__ __align__(16) __nv_bfloat16 g_xh1[BB*RCH*TT];
__device__ __align__(16) __nv_bfloat16 g_xl1[BB*RCH*TT];
__device__ __align__(16) __nv_bfloat16 g_ch[BB*ACH*TT];
__device__ __align__(16) __nv_bfloat16 g_cl[BB*ACH*TT];

// weights: 11 chunks of [128 m][32 k] per layer; chunks 0..8 permuted m
// (row m <-> channel (m&1 ? m/2+64 : m/2)); 9,10 = OW k-halves natural m.
__device__ __align__(16) __nv_bfloat16 g_wh[(size_t)NLAYERS * WPERL];
__device__ __align__(16) __nv_bfloat16 g_wl[(size_t)NLAYERS * WPERL];

static __device__ __forceinline__ float tanhapx(float x) {
    float r; asm("tanh.approx.f32 %0, %1;" : "=f"(r) : "f"(x)); return r;
}
static __device__ __forceinline__ float gatef(float a, float b) {
    return tanhapx(a) * (0.5f * tanhapx(0.5f * b) + 0.5f);
}
static __device__ __forceinline__ uint32_t smem_u32(const void* p) {
    uint32_t a;
    asm("{ .reg .u64 t; cvta.to.shared.u64 t, %1; cvt.u32.u64 %0, t; }"
        : "=r"(a) : "l"(p));
    return a;
}
static __device__ __forceinline__ void cpa16(uint32_t d, const void* s, bool p) {
    asm volatile("cp.async.cg.shared.global [%0], [%1], 16, %2;"
                 :: "r"(d), "l"(s), "r"(p ? 16 : 0));
}
static __device__ __forceinline__ void cpa4(uint32_t d, const void* s, bool p) {
    asm volatile("cp.async.ca.shared.global [%0], [%1], 4, %2;"
                 :: "r"(d), "l"(s), "r"(p ? 4 : 0));
}
template<int N>
static __device__ __forceinline__ void cp_wait() {
    asm volatile("cp.async.wait_group %0;" :: "n"(N));
}
static __device__ __forceinline__ void cp_commit() {
    asm volatile("cp.async.commit_group;");
}
#define MB_INIT(mb, n) \
    asm volatile("mbarrier.init.shared.b64 [%0], %1;" :: "r"(mb), "r"(n) : "memory")
#define MB_ARRIVE(mb) \
    asm volatile("mbarrier.arrive.shared.b64 _, [%0];" :: "r"(mb) : "memory")
#define CP_MB_ARRIVE(mb) \
    asm volatile("cp.async.mbarrier.arrive.noinc.shared.b64 [%0];" :: "r"(mb) : "memory")
#define MB_WAIT(mb, ph) do {                                                    \
    uint32_t _m = (mb), _p = (ph), _done;                                       \
    asm volatile("{ .reg .pred p; mbarrier.try_wait.parity.acquire.cta.shared::cta.b64 p, [%1], %2;" \
                 " selp.b32 %0, 1, 0, p; }" : "=r"(_done) : "r"(_m), "r"(_p) : "memory"); \
    if (!_done) {                                                               \
        asm volatile("{ .reg .pred P1; WL_%=: mbarrier.try_wait.parity.acquire.cta.shared::cta.b64 P1, [%0], %1, 0x989680;" \
                     " @P1 bra.uni WD_%=; bra.uni WL_%=; WD_%=: }"              \
                     :: "r"(_m), "r"(_p) : "memory");                           \
    }                                                                           \
} while (0)

// ---------------------------------------------------------------------------
__global__ void k_prep(const float* __restrict__ cw, const float* __restrict__ aw,
                       const float* __restrict__ ow) {
    int idx = blockIdx.x * blockDim.x + threadIdx.x;
    if (idx >= NLAYERS * WPERL) return;
    int j = idx % WPERL;
    int l = idx / WPERL;
    int c  = j >> 12;
    int m  = (j >> 5) & 127;
    int kk = j & 31;
    int mp = (m & 1) ? (m >> 1) + 64 : (m >> 1);
    float v;
    if (c < 6) {
        int tap = c >> 1, ci = 32 * (c & 1) + kk;
        v = cw[((size_t)(l * GCH + mp) * RCH + ci) * 3 + tap];
    } else if (c == 6) {
        v = aw[(size_t)(l * GCH + mp) * ACH + kk];
    } else if (c == 7) {
        v = aw[(size_t)(l * GCH + mp) * ACH + 32 + kk];
    } else if (c == 8) {
        v = (kk < 16) ? aw[(size_t)(l * GCH + mp) * ACH + 64 + kk] : 0.f;
    } else {
        v = ow[(size_t)(l * GCH + m) * 64 + 32 * (c - 9) + kk];
    }
    __nv_bfloat16 h = __float2bfloat16(v);
    g_wh[idx] = h;
    g_wl[idx] = __float2bfloat16(v - __bfloat162float(h));
}

__global__ void k_prep_c(const float* __restrict__ cond) {
    int idx = blockIdx.x * blockDim.x + threadIdx.x;
    if (idx >= BB * ACH * TT) return;
    float v = cond[idx];
    __nv_bfloat16 h = __float2bfloat16(v);
    g_ch[idx] = h;
    g_cl[idx] = __float2bfloat16(v - __bfloat162float(h));
}

__global__ void k_first(const float* __restrict__ x,
                        const float* __restrict__ fw,
                        const float* __restrict__ fb) {
    int idx = blockIdx.x * blockDim.x + threadIdx.x;
    int r = idx >> 16;
    int p = idx & (NPOS - 1);
    int b = p >> 13;
    int t = p & (TT - 1);
    float v = fw[r] * x[p] + fb[r];
    size_t xi = (size_t)(b * RCH + r) * TT + t;
    g_xa[xi] = v;
    __nv_bfloat16 h = __float2bfloat16(v);
    g_xh0[xi] = h;
    g_xl0[xi] = __float2bfloat16(v - __bfloat162float(h));
    g_skip[(size_t)(b * SCH + r) * TT + t] = 0.f;
}

// ---- bf16x3 mma over one K=32 tile: W[128][40] hi/lo, X[32][stride] hi/lo ---
template<int XSTR>
static __device__ __forceinline__ void mma_k32(
        wmma::fragment<wmma::accumulator, 16, 16, 16, float> (&acc)[2],
        const __nv_bfloat16* __restrict__ wh, const __nv_bfloat16* __restrict__ wl,
        const __nv_bfloat16* __restrict__ xh, const __nv_bfloat16* __restrict__ xl,
        int m0, int n0) {
#pragma unroll 1
    for (int ks = 0; ks < 2; ks++) {
        wmma::fragment<wmma::matrix_a, 16, 16, 16, __nv_bfloat16, wmma::row_major> ah, al;
        wmma::load_matrix_sync(ah, wh + m0 * 40 + 16 * ks, 40);
        wmma::load_matrix_sync(al, wl + m0 * 40 + 16 * ks, 40);
#pragma unroll
        for (int nt = 0; nt < 2; nt++) {
            wmma::fragment<wmma::matrix_b, 16, 16, 16, __nv_bfloat16, wmma::row_major> bf;
            const int bo = 16 * ks * XSTR + n0 + 16 * nt;
            wmma::load_matrix_sync(bf, xh + bo, XSTR);
            wmma::mma_sync(acc[nt], ah, bf, acc[nt]);
            wmma::mma_sync(acc[nt], al, bf, acc[nt]);
            wmma::load_matrix_sync(bf, xl + bo, XSTR);
            wmma::mma_sync(acc[nt], ah, bf, acc[nt]);
        }
    }
}

// ---------------------------------------------------------------------------
// warp-specialized fused layer.
// ---------------------------------------------------------------------------
__global__ void __launch_bounds__(THR, 2)
k_layer(int l, int d, int flip,
        const float* __restrict__ conv_b, const float* __restrict__ out_b,
        const float* __restrict__ mask) {
    extern __shared__ char smraw[];
    const uint32_t sb = smem_u32(smraw);
    // mbarriers: full[s] at sb + 16*s, empty[s] at sb + 16*s + 8
    const int tid  = threadIdx.x;
    const int wid  = tid >> 5;
    const int lane = tid & 31;
    const int p0   = blockIdx.x * NT;
    const int b    = p0 >> 13;
    const int tb   = p0 & (TT - 1);

    if (tid == 0) {
#pragma unroll
        for (int s = 0; s < 3; s++) {
            MB_INIT(sb + 16 * s, 32);       // full: 32 producer threads
            MB_INIT(sb + 16 * s + 8, 16);   // empty: 16 consumer warps
        }
    }
    __syncthreads();

    const __nv_bfloat16* gwh = g_wh + (size_t)l * WPERL;
    const __nv_bfloat16* gwl = g_wl + (size_t)l * WPERL;
    const float* xin  = flip ? g_xb : g_xa;
    float*       xout = flip ? g_xa : g_xb;
    const __nv_bfloat16* iph = flip ? g_xh1 : g_xh0;
    const __nv_bfloat16* ipl = flip ? g_xl1 : g_xl0;
    __nv_bfloat16* oph = flip ? g_xh0 : g_xh1;
    __nv_bfloat16* opl = flip ? g_xl0 : g_xl1;

    wmma::fragment<wmma::accumulator, 16, 16, 16, float> acc[2];
    wmma::fill_fragment(acc[0], 0.f);
    wmma::fill_fragment(acc[1], 0.f);
    const int m0 = (wid & 7) * 16;
    const int nh = (wid >> 3) & 1;
    const int n0 = nh * 32;

    if (wid == 16) {
        // ===================== PRODUCER WARP ================================
        const __nv_bfloat16* xbh = iph + (size_t)b * RCH * TT;
        const __nv_bfloat16* xbl = ipl + (size_t)b * RCH * TT;
        const __nv_bfloat16* cbh = g_ch + (size_t)b * ACH * TT;
        const __nv_bfloat16* cbl = g_cl + (size_t)b * ACH * TT;
#pragma unroll 1
        for (int ch = 0; ch < NCHUNK; ch++) {
            const int s = ch - (ch >= 3 ? 3 : 0) - (ch >= 6 ? 3 : 0) - (ch >= 9 ? 3 : 0);
            const int r = ch / 3;
            if (r >= 1) MB_WAIT(sb + 16 * s + 8, (r - 1) & 1);
            const uint32_t bw = sb + SM_BUFS + s * BUFB;
            const __nv_bfloat16* gh = gwh + ch * 4096;
            const __nv_bfloat16* gl = gwl + ch * 4096;
            // W: 512 cpa16 per plane over 32 threads
#pragma unroll
            for (int rep = 0; rep < 16; rep++) {
                int i = rep * 32 + lane;
                int m = i >> 2, j = i & 3;
                uint32_t doff = m * 80 + j * 16;
                cpa16(bw + doff,         gh + m * 32 + j * 8, true);
                cpa16(bw + 10240 + doff, gl + m * 32 + j * 8, true);
            }
            bool scalar_done = false;
            const uint32_t xw = bw + 20480;
            if (ch < 6) {
                const int kh = ch & 1;
                const int off = ((ch >> 1) - 1) * d;
                const __nv_bfloat16* ph = xbh + (size_t)(32 * kh) * TT;
                const __nv_bfloat16* pl = xbl + (size_t)(32 * kh) * TT;
                if ((off & 7) == 0) {
                    // FIXED: 32 rows x 8 chunks of 16B = full 64 positions
#pragma unroll
                    for (int rep = 0; rep < 8; rep++) {
                        int i = rep * 32 + lane;
                        int kk = i >> 3, j = i & 7;
                        int t0 = tb + j * 8 + off;
                        bool ok = (unsigned)t0 <= (unsigned)(TT - 8);
                        size_t so = (size_t)kk * TT + (ok ? t0 : 0);
                        cpa16(xw + kk * 144 + j * 16,        ph + so, ok);
                        cpa16(xw + 4608 + kk * 144 + j * 16, pl + so, ok);
                    }
                } else if ((off & 1) == 0) {
#pragma unroll
                    for (int rep = 0; rep < 32; rep++) {
                        int i = rep * 32 + lane;
                        int kk = i >> 5, q = i & 31;
                        int t0 = tb + 2 * q + off;
                        bool ok = (unsigned)t0 <= (unsigned)(TT - 2);
                        size_t so = (size_t)kk * TT + (ok ? t0 : 0);
                        cpa4(xw + kk * 144 + q * 4,        ph + so, ok);
                        cpa4(xw + 4608 + kk * 144 + q * 4, pl + so, ok);
                    }
                } else {
                    // d == 1: scalar sync fallback
                    __nv_bfloat16* xh = (__nv_bfloat16*)(smraw + SM_BUFS + s * BUFB + 20480);
                    __nv_bfloat16* xl = xh + 2304;
                    const __nv_bfloat16 z0 = __float2bfloat16(0.f);
#pragma unroll 1
                    for (int i = lane; i < 2048; i += 32) {
                        int kk = i >> 6, pp = i & 63;
                        int t0 = tb + pp + off;
                        bool ok = (unsigned)t0 < TT;
                        size_t so = (size_t)kk * TT + (ok ? t0 : 0);
                        xh[kk * 72 + pp] = ok ? ph[so] : z0;
                        xl[kk * 72 + pp] = ok ? pl[so] : z0;
                    }
                    scalar_done = true;
                }
            } else if (ch < 9) {
                const int a0 = 32 * (ch - 6);
                // FIXED: 32 rows x 8 chunks of 16B
#pragma unroll
                for (int rep = 0; rep < 8; rep++) {
                    int i = rep * 32 + lane;
                    int kk = i >> 3, j = i & 7;
                    bool ok = (ch < 8) || (kk < 16);
                    size_t so = ok ? (size_t)(a0 + kk) * TT + tb + j * 8 : 0;
                    cpa16(xw + kk * 144 + j * 16,        cbh + so, ok);
                    cpa16(xw + 4608 + kk * 144 + j * 16, cbl + so, ok);
                }
            }
            cp_commit();
            if (scalar_done) {
                cp_wait<0>();
                MB_ARRIVE(sb + 16 * s);
            } else {
                CP_MB_ARRIVE(sb + 16 * s);
            }
        }
    } else {
        // ===================== CONSUMER WARPS ===============================
#pragma unroll 1
        for (int ch = 0; ch < 9; ch++) {
            const int s = ch - (ch >= 3 ? 3 : 0) - (ch >= 6 ? 3 : 0);
            const int r = ch / 3;
            MB_WAIT(sb + 16 * s, r & 1);
            const __nv_bfloat16* buf =
                (const __nv_bfloat16*)(smraw + SM_BUFS + s * BUFB);
            mma_k32<72>(acc, buf, buf + 5120, buf + 10240, buf + 12544, m0, n0);
            __syncwarp();
            if (lane == 0) MB_ARRIVE(sb + 16 * s + 8);
        }
    }
    __syncthreads();   // mainloop done; stage2 + stage0/1 X regions free

    // ===== gate: two n-half passes through fsm (stage2 overlay) =============
    float* fsm = (float*)(smraw + SM_BUFS + 2 * BUFB);          // 128x36 f32
    __nv_bfloat16* zh = (__nv_bfloat16*)(smraw + SM_BUFS + 20480);           // [64][72]
    __nv_bfloat16* zl = (__nv_bfloat16*)(smraw + SM_BUFS + BUFB + 20480);    // [64][72]
    const float* cbp = conv_b + l * GCH;
#pragma unroll 1
    for (int half = 0; half < 2; half++) {
        if (wid < 16 && nh == half) {
            wmma::store_matrix_sync(fsm + m0 * 36,      acc[0], 36, wmma::mem_row_major);
            wmma::store_matrix_sync(fsm + m0 * 36 + 16, acc[1], 36, wmma::mem_row_major);
        }
        __syncthreads();
#pragma unroll 1
        for (int i = tid; i < 2048; i += THR) {
            int c = i >> 5, j = i & 31;
            float a = fsm[(2 * c) * 36 + j] + cbp[c];
            float g = fsm[(2 * c + 1) * 36 + j] + cbp[c + 64];
            float z = gatef(a, g);
            __nv_bfloat16 h = __float2bfloat16(z);
            int n = 32 * half + j;
            zh[c * 72 + n] = h;
            zl[c * 72 + n] = __float2bfloat16(z - __bfloat162float(h));
        }
        __syncthreads();
    }

    // ===== GEMM2: OW (stages 0,1 W) x Z ======================================
    if (wid < 16) {
        wmma::fill_fragment(acc[0], 0.f);
        wmma::fill_fragment(acc[1], 0.f);
        MB_WAIT(sb + 16 * 0, 1);   // full[0] phase 3 (chunk 9)
        MB_WAIT(sb + 16 * 1, 1);   // full[1] phase 3 (chunk 10)
        const __nv_bfloat16* w0 = (const __nv_bfloat16*)(smraw + SM_BUFS);
        const __nv_bfloat16* w1 = (const __nv_bfloat16*)(smraw + SM_BUFS + BUFB);
        mma_k32<72>(acc, w0, w0 + 5120, zh, zl, m0, n0);
        mma_k32<72>(acc, w1, w1 + 5120, zh + 32 * 72, zl + 32 * 72, m0, n0);
    }

    // ===== epilogue: two n-half passes =======================================
    const float* obp = out_b + l * (RCH + SCH);
#pragma unroll 1
    for (int half = 0; half < 2; half++) {
        __syncthreads();
        if (wid < 16 && nh == half) {
            wmma::store_matrix_sync(fsm + m0 * 36,      acc[0], 36, wmma::mem_row_major);
            wmma::store_matrix_sync(fsm + m0 * 36 + 16, acc[1], 36, wmma::mem_row_major);
        }
        __syncthreads();
#pragma unroll 1
        for (int i = tid; i < 4096; i += THR) {
            int r = i >> 5, j = i & 31;
            int t = tb + 32 * half + j;
            float o = fsm[r * 36 + j] + obp[r];
            float m = mask[p0 + 32 * half + j];
            if (r < RCH) {
                size_t xi = ((size_t)(b * RCH + r) << 13) + t;
                float val = fmaf(o, m, xin[xi]);
                xout[xi] = val;
                __nv_bfloat16 h = __float2bfloat16(val);
                oph[xi] = h;
                opl[xi] = __float2bfloat16(val - __bfloat162float(h));
            } else {
                size_t si = ((size_t)(b * SCH + r - RCH) << 13) + t;
                g_skip[si] += o * m;
            }
        }
    }
}

// ---------------------------------------------------------------------------
__global__ void k_last(const float* __restrict__ w1, const float* __restrict__ b1,
                       const float* __restrict__ w2, const float* __restrict__ b2,
                       float* __restrict__ out) {
    __shared__ float w1t[64 * 64];
    __shared__ float w2s[64];
    __shared__ float b1s[64];
    const int tid = threadIdx.x;
    for (int idx = tid; idx < 64 * 64; idx += 256) {
        int i = idx >> 6, j = idx & 63;
        w1t[i * 64 + j] = w1[j * 64 + i];
    }
    if (tid < 64) { w2s[tid] = w2[tid]; b1s[tid] = b1[tid]; }
    __syncthreads();

    const int p = blockIdx.x * 256 + tid;
    const int b = p >> 13;
    const int t = p & (TT - 1);

    float acc[64];
#pragma unroll
    for (int j = 0; j < 64; j++) acc[j] = b1s[j];

    const float* sp = g_skip + (size_t)b * SCH * TT + t;
    for (int i = 0; i < 64; i++) {
        float sv = fmaxf(sp[i * TT], 0.f);
#pragma unroll
        for (int j = 0; j < 64; j += 4) {
            float4 w = *(const float4*)(w1t + i * 64 + j);
            acc[j]     = fmaf(w.x, sv, acc[j]);
            acc[j + 1] = fmaf(w.y, sv, acc[j + 1]);
            acc[j + 2] = fmaf(w.z, sv, acc[j + 2]);
            acc[j + 3] = fmaf(w.w, sv, acc[j + 3]);
        }
    }
    float y = b2[0];
#pragma unroll
    for (int j = 0; j < 64; j++) y = fmaf(w2s[j], fmaxf(acc[j], 0.f), y);
    out[p] = y;
}

// ---------------------------------------------------------------------------
extern "C" void kernel_launch(void* const* d_in, const int* in_sizes, int n_in,
                              void* d_out, int out_size) {
    const float* x      = (const float*)d_in[0];
    const float* x_mask = (const float*)d_in[1];
    const float* c      = (const float*)d_in[2];
    const float* fw     = (const float*)d_in[3];
    const float* fb     = (const float*)d_in[4];
    const float* conv_w = (const float*)d_in[5];
    const float* conv_b = (const float*)d_in[6];
    const float* aux_w  = (const float*)d_in[7];
    const float* out_w  = (const float*)d_in[8];
    const float* out_b  = (const float*)d_in[9];
    const float* w1     = (const float*)d_in[10];
    const float* b1     = (const float*)d_in[11];
    const float* w2     = (const float*)d_in[12];
    const float* b2     = (const float*)d_in[13];

    cudaFuncSetAttribute(k_layer, cudaFuncAttributeMaxDynamicSharedMemorySize,
                         SMEM_TOTAL);

    int nprep = NLAYERS * WPERL;
    k_prep<<<(nprep + 511) / 512, 512>>>(conv_w, aux_w, out_w);
    k_prep_c<<<(BB * ACH * TT + 511) / 512, 512>>>(c);
    k_first<<<(RCH * NPOS) / 512, 512>>>(x, fw, fb);

    for (int l = 0; l < NLAYERS; l++) {
        int d = 1 << (l % 10);
        k_layer<<<NPOS / NT, THR, SMEM_TOTAL>>>(
            l, d, l & 1, conv_b, out_b, x_mask);
    }

    k_last<<<NPOS / 256, 256>>>(w1, b1, w2, b2, (float*)d_out);
}